// round 3
// baseline (speedup 1.0000x reference)
#include <cuda_runtime.h>
#include <math.h>

// ---------------- scratch (static device globals; no allocations allowed) ----------------
// B=8, S=1024, H=8, D=512 -> projected tensors are (8192, 4096) fp32
__device__ float g_q[8192UL * 4096];
__device__ float g_k[8192UL * 4096];
__device__ float g_v[8192UL * 4096];
__device__ float g_ctx[8192UL * 4096];
// fallback attn buffer in case attn is NOT part of d_out
__device__ float g_attn_fb[64UL * 1024 * 1024];

#define BMT 64
#define BNT 64
#define BKT 16

// ---------------------------------------------------------------------------
// Generic 64x64x16 register-blocked fp32 GEMM tile.
// TB=false: C = A(MxK, lda) * B(KxN, ldb)
// TB=true : C = A(MxK, lda) * B(NxK, ldb)^T
// All of M, N divisible by 64; K divisible by 16; all pointers 16B-aligned rows.
// ---------------------------------------------------------------------------
template <bool TB, bool BIAS>
__device__ __forceinline__ void gemm_tile64(
    const float* __restrict__ A, int lda,
    const float* __restrict__ B, int ldb,
    float* __restrict__ C, int ldc,
    int K, const float* __restrict__ bias)
{
    __shared__ float AsT[BKT][BMT];   // transposed A tile: AsT[k][m]
    __shared__ float Bs[BKT][BNT];    // Bs[k][n]

    const int tid = threadIdx.x;      // 256 threads
    const int tx = tid & 15;          // 0..15  (n direction)
    const int ty = tid >> 4;          // 0..15  (m direction)

    const int m0 = blockIdx.y * BMT;
    const int n0 = blockIdx.x * BNT;

    // A-load mapping: 64 rows x 16 k, 4 consecutive k per thread (float4)
    const int la_m = tid & 63;
    const int la_k = (tid >> 6) << 2;

    float acc[4][4] = {};

    for (int k0 = 0; k0 < K; k0 += BKT) {
        // ---- load A tile (transposed store) ----
        float4 av = *reinterpret_cast<const float4*>(
            &A[(size_t)(m0 + la_m) * lda + k0 + la_k]);
        AsT[la_k + 0][la_m] = av.x;
        AsT[la_k + 1][la_m] = av.y;
        AsT[la_k + 2][la_m] = av.z;
        AsT[la_k + 3][la_m] = av.w;

        // ---- load B tile ----
        if (!TB) {
            const int lb_k = tid >> 4;          // 0..15
            const int lb_n = (tid & 15) << 2;   // 0,4,...,60
            float4 bv = *reinterpret_cast<const float4*>(
                &B[(size_t)(k0 + lb_k) * ldb + n0 + lb_n]);
            *reinterpret_cast<float4*>(&Bs[lb_k][lb_n]) = bv;
        } else {
            const int lb_n = tid & 63;
            const int lb_k = (tid >> 6) << 2;
            float4 bv = *reinterpret_cast<const float4*>(
                &B[(size_t)(n0 + lb_n) * ldb + k0 + lb_k]);
            Bs[lb_k + 0][lb_n] = bv.x;
            Bs[lb_k + 1][lb_n] = bv.y;
            Bs[lb_k + 2][lb_n] = bv.z;
            Bs[lb_k + 3][lb_n] = bv.w;
        }
        __syncthreads();

        // ---- compute ----
#pragma unroll
        for (int kk = 0; kk < BKT; kk++) {
            float4 a4 = *reinterpret_cast<const float4*>(&AsT[kk][ty << 2]);
            float4 b4 = *reinterpret_cast<const float4*>(&Bs[kk][tx << 2]);
            float a[4] = {a4.x, a4.y, a4.z, a4.w};
            float b[4] = {b4.x, b4.y, b4.z, b4.w};
#pragma unroll
            for (int i = 0; i < 4; i++)
#pragma unroll
                for (int j = 0; j < 4; j++)
                    acc[i][j] = fmaf(a[i], b[j], acc[i][j]);
        }
        __syncthreads();
    }

    // ---- store ----
#pragma unroll
    for (int i = 0; i < 4; i++) {
        const int m = m0 + (ty << 2) + i;
#pragma unroll
        for (int j = 0; j < 4; j++) {
            const int n = n0 + (tx << 2) + j;
            float v = acc[i][j];
            if (BIAS) v += bias[n];
            C[(size_t)m * ldc + n] = v;
        }
    }
}

// ---------------- projection / output GEMM: Y = X*W + b ----------------
__global__ __launch_bounds__(256) void proj_kernel(
    const float* __restrict__ X, const float* __restrict__ W,
    const float* __restrict__ bias, float* __restrict__ Y, int K, int N)
{
    gemm_tile64<false, true>(X, K, W, N, Y, N, K, bias);
}

// ---------------- logits = Q_bh * K_bh^T (batched over z = b*8+h) ----------------
__global__ __launch_bounds__(256) void qk_kernel(
    const float* __restrict__ Q, const float* __restrict__ Kt,
    float* __restrict__ logits)
{
    const int z = blockIdx.z;
    const int b = z >> 3, h = z & 7;
    const float* A = Q + (size_t)b * 1024 * 4096 + (size_t)h * 512;
    const float* B = Kt + (size_t)b * 1024 * 4096 + (size_t)h * 512;
    float* C = logits + (size_t)z * 1024 * 1024;
    gemm_tile64<true, false>(A, 4096, B, 4096, C, 1024, 512, nullptr);
}

// ---------------- masked softmax, in place on attn buffer ----------------
// One block (256 threads) per row of 1024 logits.
__global__ __launch_bounds__(256) void softmax_kernel(
    float* __restrict__ attn, const float* __restrict__ mask)
{
    const int r = blockIdx.x;             // 0 .. 65535  (= ((b*8+h)*1024)+q)
    const int q = r & 1023;
    const int b = r >> 13;                // r / (8*1024)
    float* row = attn + (size_t)r * 1024;
    const float* mrow = mask + ((size_t)b * 1024 + q) * 1024;

    const int tid = threadIdx.x;
    const float scale = 0.044194173824159216f;  // 1/sqrt(512)

    float vals[4];
    float mx = -INFINITY;
#pragma unroll
    for (int j = 0; j < 4; j++) {
        const int c = tid + j * 256;
        float v = row[c] * scale + mrow[c] * (-1e9f);
        vals[j] = v;
        mx = fmaxf(mx, v);
    }

    __shared__ float sred[8];
    // warp reduce max
#pragma unroll
    for (int o = 16; o > 0; o >>= 1)
        mx = fmaxf(mx, __shfl_xor_sync(0xffffffffu, mx, o));
    if ((tid & 31) == 0) sred[tid >> 5] = mx;
    __syncthreads();
    if (tid < 32) {
        float v = (tid < 8) ? sred[tid] : -INFINITY;
#pragma unroll
        for (int o = 4; o > 0; o >>= 1)
            v = fmaxf(v, __shfl_xor_sync(0xffffffffu, v, o));
        if (tid == 0) sred[0] = v;
    }
    __syncthreads();
    mx = sred[0];

    float s = 0.f;
#pragma unroll
    for (int j = 0; j < 4; j++) {
        vals[j] = __expf(vals[j] - mx);
        s += vals[j];
    }
#pragma unroll
    for (int o = 16; o > 0; o >>= 1)
        s += __shfl_xor_sync(0xffffffffu, s, o);
    __syncthreads();
    if ((tid & 31) == 0) sred[tid >> 5] = s;
    __syncthreads();
    if (tid < 32) {
        float v = (tid < 8) ? sred[tid] : 0.f;
#pragma unroll
        for (int o = 4; o > 0; o >>= 1)
            v += __shfl_xor_sync(0xffffffffu, v, o);
        if (tid == 0) sred[0] = v;
    }
    __syncthreads();
    const float inv = 1.0f / sred[0];

#pragma unroll
    for (int j = 0; j < 4; j++)
        row[tid + j * 256] = vals[j] * inv;
}

// ---------------- ctx_bh = attn_bh * V_bh (batched) ----------------
__global__ __launch_bounds__(256) void av_kernel(
    const float* __restrict__ attn, const float* __restrict__ V,
    float* __restrict__ ctx)
{
    const int z = blockIdx.z;
    const int b = z >> 3, h = z & 7;
    const float* A = attn + (size_t)z * 1024 * 1024;
    const float* B = V + (size_t)b * 1024 * 4096 + (size_t)h * 512;
    float* C = ctx + (size_t)b * 1024 * 4096 + (size_t)h * 512;
    gemm_tile64<false, false>(A, 1024, B, 4096, C, 4096, 1024, nullptr);
}

// ---------------------------------------------------------------------------
extern "C" void kernel_launch(void* const* d_in, const int* in_sizes, int n_in,
                              void* d_out, int out_size)
{
    // metadata order = setup_inputs dict order:
    const float* v_ip = (const float*)d_in[0];
    const float* k_ip = (const float*)d_in[1];
    const float* q_ip = (const float*)d_in[2];
    const float* mask = (const float*)d_in[3];
    const float* wq   = (const float*)d_in[4];
    const float* bq   = (const float*)d_in[5];
    const float* wk   = (const float*)d_in[6];
    const float* bk   = (const float*)d_in[7];
    const float* wv   = (const float*)d_in[8];
    const float* bv   = (const float*)d_in[9];
    const float* wo   = (const float*)d_in[10];
    const float* bo   = (const float*)d_in[11];

    float *Q, *K, *V, *CTX, *ATTN_FB;
    cudaGetSymbolAddress((void**)&Q,   g_q);
    cudaGetSymbolAddress((void**)&K,   g_k);
    cudaGetSymbolAddress((void**)&V,   g_v);
    cudaGetSymbolAddress((void**)&CTX, g_ctx);
    cudaGetSymbolAddress((void**)&ATTN_FB, g_attn_fb);

    const size_t OUT_ELEMS  = 8UL * 1024 * 512;        // 4,194,304
    const size_t ATTN_ELEMS = 64UL * 1024 * 1024;      // 67,108,864
    float* out = (float*)d_out;
    float* attn = ((size_t)out_size >= OUT_ELEMS + ATTN_ELEMS)
                      ? (out + OUT_ELEMS)
                      : ATTN_FB;

    // 1) projections: (8192x512)@(512x4096)
    {
        dim3 grid(4096 / BNT, 8192 / BMT);
        proj_kernel<<<grid, 256>>>(q_ip, wq, bq, Q, 512, 4096);
        proj_kernel<<<grid, 256>>>(k_ip, wk, bk, K, 512, 4096);
        proj_kernel<<<grid, 256>>>(v_ip, wv, bv, V, 512, 4096);
    }

    // 2) logits = Q Kt^T per (b,h)
    {
        dim3 grid(1024 / BNT, 1024 / BMT, 64);
        qk_kernel<<<grid, 256>>>(Q, K, attn);
    }

    // 3) masked softmax in place
    softmax_kernel<<<64 * 1024, 256>>>(attn, mask);

    // 4) ctx = attn @ V
    {
        dim3 grid(512 / BNT, 1024 / BMT, 64);
        av_kernel<<<grid, 256>>>(attn, V, CTX);
    }

    // 5) out = ctx @ wo + bo : (8192x4096)@(4096x512)
    {
        dim3 grid(512 / BNT, 8192 / BMT);
        proj_kernel<<<grid, 256>>>(CTX, wo, bo, out, 4096, 512);
    }
}

// round 5
// speedup vs baseline: 1.6913x; 1.6913x over previous
#include <cuda_runtime.h>
#include <cuda_bf16.h>
#include <math.h>
#include <stdint.h>

// ---------------- scratch (static device globals; no allocations allowed) ----------------
__device__ float g_q[8192UL * 4096];
__device__ float g_k[8192UL * 4096];
__device__ float g_v[8192UL * 4096];
__device__ float g_ctx[8192UL * 4096];
__device__ float g_attn_fb[64UL * 1024 * 1024];

#define BM 128
#define BN 128
#define BK 32
#define PAD 40   // bf16 per smem row (80 bytes) -> conflict-free ldmatrix

__device__ __forceinline__ uint32_t cvta_s(const void* p) {
    return (uint32_t)__cvta_generic_to_shared(p);
}

__device__ __forceinline__ void ldsm4(uint32_t* r, uint32_t a) {
    asm volatile("ldmatrix.sync.aligned.m8n8.x4.shared.b16 {%0,%1,%2,%3},[%4];\n"
        : "=r"(r[0]), "=r"(r[1]), "=r"(r[2]), "=r"(r[3]) : "r"(a));
}

__device__ __forceinline__ void mma_bf16(float* d, const uint32_t* a, const uint32_t* b) {
    asm volatile(
        "mma.sync.aligned.m16n8k16.row.col.f32.bf16.bf16.f32 "
        "{%0,%1,%2,%3},{%4,%5,%6,%7},{%8,%9},{%0,%1,%2,%3};\n"
        : "+f"(d[0]), "+f"(d[1]), "+f"(d[2]), "+f"(d[3])
        : "r"(a[0]), "r"(a[1]), "r"(a[2]), "r"(a[3]), "r"(b[0]), "r"(b[1]));
}

__device__ __forceinline__ void split_bf16(float x, __nv_bfloat16& h, __nv_bfloat16& l) {
    h = __float2bfloat16(x);
    l = __float2bfloat16(x - __bfloat162float(h));
}

// ---------------------------------------------------------------------------
// 128x128 block, 8 warps of 64x32, bf16x3 split-fp32 tensor-core GEMM.
// TB=false: C = A(MxK,lda) * B(KxN,ldb)    TB=true: C = A * B(NxK,ldb)^T
// M,N % 128 == 0, K % 32 == 0
// ---------------------------------------------------------------------------
template <bool TB, bool BIAS>
__device__ __forceinline__ void gemm_mma(
    const float* __restrict__ A, int lda,
    const float* __restrict__ B, int ldb,
    float* __restrict__ C, int ldc,
    int K, const float* __restrict__ bias)
{
    __shared__ __nv_bfloat16 sAh[BM][PAD], sAl[BM][PAD];
    __shared__ __nv_bfloat16 sBh[BN][PAD], sBl[BN][PAD];

    const int tid  = threadIdx.x;     // 256
    const int lane = tid & 31;
    const int warp = tid >> 5;
    const int wm   = warp >> 2;       // 0..1  (M dir, 64 rows)
    const int wn   = warp & 3;        // 0..3  (N dir, 32 cols)
    const int m0   = blockIdx.y * BM;
    const int n0   = blockIdx.x * BN;

    // ldmatrix per-thread address components (bytes)
    const int offA = (lane & 15) * (PAD * 2) + (lane >> 4) * 16;
    const int offB = (((lane >> 4) & 1) * 8 + (lane & 7)) * (PAD * 2) + ((lane >> 3) & 1) * 16;

    const uint32_t baseAh = cvta_s(&sAh[0][0]) + wm * 64 * (PAD * 2) + offA;
    const uint32_t baseAl = cvta_s(&sAl[0][0]) + wm * 64 * (PAD * 2) + offA;
    const uint32_t baseBh = cvta_s(&sBh[0][0]) + wn * 32 * (PAD * 2) + offB;
    const uint32_t baseBl = cvta_s(&sBl[0][0]) + wn * 32 * (PAD * 2) + offB;

    float acc[4][4][4] = {};   // [m16 frag][n8 frag][c regs]

    for (int k0 = 0; k0 < K; k0 += BK) {
        // ---- A tile: 128 rows x 32 k, float4 loads, split to hi/lo ----
#pragma unroll
        for (int p = 0; p < 4; p++) {
            const int r = (tid >> 3) + p * 32;
            const int c = (tid & 7) * 4;
            float4 v = *reinterpret_cast<const float4*>(
                &A[(size_t)(m0 + r) * lda + k0 + c]);
            __nv_bfloat16 h[4], l[4];
            split_bf16(v.x, h[0], l[0]); split_bf16(v.y, h[1], l[1]);
            split_bf16(v.z, h[2], l[2]); split_bf16(v.w, h[3], l[3]);
            __nv_bfloat162* ph = reinterpret_cast<__nv_bfloat162*>(&sAh[r][c]);
            __nv_bfloat162* pl = reinterpret_cast<__nv_bfloat162*>(&sAl[r][c]);
            __nv_bfloat162 t;
            t.x = h[0]; t.y = h[1]; ph[0] = t;
            t.x = h[2]; t.y = h[3]; ph[1] = t;
            t.x = l[0]; t.y = l[1]; pl[0] = t;
            t.x = l[2]; t.y = l[3]; pl[1] = t;
        }

        // ---- B tile -> smem [n][k] ----
        if (TB) {
#pragma unroll
            for (int p = 0; p < 4; p++) {
                const int r = (tid >> 3) + p * 32;     // n index
                const int c = (tid & 7) * 4;           // k index
                float4 v = *reinterpret_cast<const float4*>(
                    &B[(size_t)(n0 + r) * ldb + k0 + c]);
                __nv_bfloat16 h[4], l[4];
                split_bf16(v.x, h[0], l[0]); split_bf16(v.y, h[1], l[1]);
                split_bf16(v.z, h[2], l[2]); split_bf16(v.w, h[3], l[3]);
                __nv_bfloat162* ph = reinterpret_cast<__nv_bfloat162*>(&sBh[r][c]);
                __nv_bfloat162* pl = reinterpret_cast<__nv_bfloat162*>(&sBl[r][c]);
                __nv_bfloat162 t;
                t.x = h[0]; t.y = h[1]; ph[0] = t;
                t.x = h[2]; t.y = h[3]; ph[1] = t;
                t.x = l[0]; t.y = l[1]; pl[0] = t;
                t.x = l[2]; t.y = l[3]; pl[1] = t;
            }
        } else {
            // B is [K][N]; transpose into [n][k]
#pragma unroll
            for (int p = 0; p < 4; p++) {
                const int kr = (tid >> 5) + p * 8;     // k index (0..31)
                const int c  = (tid & 31) * 4;         // n index
                float4 v = *reinterpret_cast<const float4*>(
                    &B[(size_t)(k0 + kr) * ldb + n0 + c]);
                __nv_bfloat16 h, l;
                split_bf16(v.x, h, l); sBh[c + 0][kr] = h; sBl[c + 0][kr] = l;
                split_bf16(v.y, h, l); sBh[c + 1][kr] = h; sBl[c + 1][kr] = l;
                split_bf16(v.z, h, l); sBh[c + 2][kr] = h; sBl[c + 2][kr] = l;
                split_bf16(v.w, h, l); sBh[c + 3][kr] = h; sBl[c + 3][kr] = l;
            }
        }
        __syncthreads();

        // ---- compute: 2 k16 steps ----
#pragma unroll
        for (int ks = 0; ks < 2; ks++) {
            uint32_t ah[4][4], al[4][4], bh[2][4], bl[2][4];
#pragma unroll
            for (int mi = 0; mi < 4; mi++) {
                ldsm4(ah[mi], baseAh + mi * 16 * (PAD * 2) + ks * 32);
                ldsm4(al[mi], baseAl + mi * 16 * (PAD * 2) + ks * 32);
            }
            ldsm4(bh[0], baseBh + ks * 32);
            ldsm4(bh[1], baseBh + 16 * (PAD * 2) + ks * 32);
            ldsm4(bl[0], baseBl + ks * 32);
            ldsm4(bl[1], baseBl + 16 * (PAD * 2) + ks * 32);

#pragma unroll
            for (int mi = 0; mi < 4; mi++) {
#pragma unroll
                for (int ni = 0; ni < 4; ni++) {
                    const uint32_t* bph = &bh[ni >> 1][(ni & 1) * 2];
                    const uint32_t* bpl = &bl[ni >> 1][(ni & 1) * 2];
                    mma_bf16(acc[mi][ni], ah[mi], bph);  // hi*hi
                    mma_bf16(acc[mi][ni], ah[mi], bpl);  // hi*lo
                    mma_bf16(acc[mi][ni], al[mi], bph);  // lo*hi
                }
            }
        }
        __syncthreads();
    }

    // ---- epilogue ----
    const int mw = m0 + wm * 64;
    const int nw = n0 + wn * 32;
#pragma unroll
    for (int mi = 0; mi < 4; mi++) {
        const int r0 = mw + mi * 16 + (lane >> 2);
#pragma unroll
        for (int ni = 0; ni < 4; ni++) {
            const int c = nw + ni * 8 + (lane & 3) * 2;
            float2 v0, v1;
            v0.x = acc[mi][ni][0]; v0.y = acc[mi][ni][1];
            v1.x = acc[mi][ni][2]; v1.y = acc[mi][ni][3];
            if (BIAS) {
                float2 bb = *reinterpret_cast<const float2*>(&bias[c]);
                v0.x += bb.x; v0.y += bb.y; v1.x += bb.x; v1.y += bb.y;
            }
            *reinterpret_cast<float2*>(&C[(size_t)r0 * ldc + c]) = v0;
            *reinterpret_cast<float2*>(&C[(size_t)(r0 + 8) * ldc + c]) = v1;
        }
    }
}

// ---------------- projection / output GEMM: Y = X*W + b ----------------
__global__ __launch_bounds__(256) void proj_kernel(
    const float* __restrict__ X, const float* __restrict__ W,
    const float* __restrict__ bias, float* __restrict__ Y, int K, int N)
{
    gemm_mma<false, true>(X, K, W, N, Y, N, K, bias);
}

// ---------------- logits = Q_bh * K_bh^T (batched) ----------------
__global__ __launch_bounds__(256) void qk_kernel(
    const float* __restrict__ Q, const float* __restrict__ Kt,
    float* __restrict__ logits)
{
    const int z = blockIdx.z;
    const int b = z >> 3, h = z & 7;
    const float* A = Q + (size_t)b * 1024 * 4096 + (size_t)h * 512;
    const float* B = Kt + (size_t)b * 1024 * 4096 + (size_t)h * 512;
    float* C = logits + (size_t)z * 1024 * 1024;
    gemm_mma<true, false>(A, 4096, B, 4096, C, 1024, 512, nullptr);
}

// ---------------- masked softmax, in place ----------------
__global__ __launch_bounds__(256) void softmax_kernel(
    float* __restrict__ attn, const float* __restrict__ mask)
{
    const int r = blockIdx.x;
    const int q = r & 1023;
    const int b = r >> 13;
    float* row = attn + (size_t)r * 1024;
    const float* mrow = mask + ((size_t)b * 1024 + q) * 1024;

    const int tid = threadIdx.x;
    const float scale = 0.044194173824159216f;  // 1/sqrt(512)

    float vals[4];
    float mx = -INFINITY;
#pragma unroll
    for (int j = 0; j < 4; j++) {
        const int c = tid + j * 256;
        float v = row[c] * scale + mrow[c] * (-1e9f);
        vals[j] = v;
        mx = fmaxf(mx, v);
    }

    __shared__ float sred[8];
#pragma unroll
    for (int o = 16; o > 0; o >>= 1)
        mx = fmaxf(mx, __shfl_xor_sync(0xffffffffu, mx, o));
    if ((tid & 31) == 0) sred[tid >> 5] = mx;
    __syncthreads();
    if (tid < 32) {
        float v = (tid < 8) ? sred[tid] : -INFINITY;
#pragma unroll
        for (int o = 4; o > 0; o >>= 1)
            v = fmaxf(v, __shfl_xor_sync(0xffffffffu, v, o));
        if (tid == 0) sred[0] = v;
    }
    __syncthreads();
    mx = sred[0];

    float s = 0.f;
#pragma unroll
    for (int j = 0; j < 4; j++) {
        vals[j] = __expf(vals[j] - mx);
        s += vals[j];
    }
#pragma unroll
    for (int o = 16; o > 0; o >>= 1)
        s += __shfl_xor_sync(0xffffffffu, s, o);
    __syncthreads();
    if ((tid & 31) == 0) sred[tid >> 5] = s;
    __syncthreads();
    if (tid < 32) {
        float v = (tid < 8) ? sred[tid] : 0.f;
#pragma unroll
        for (int o = 4; o > 0; o >>= 1)
            v += __shfl_xor_sync(0xffffffffu, v, o);
        if (tid == 0) sred[0] = v;
    }
    __syncthreads();
    const float inv = 1.0f / sred[0];

#pragma unroll
    for (int j = 0; j < 4; j++)
        row[tid + j * 256] = vals[j] * inv;
}

// ---------------- ctx_bh = attn_bh * V_bh (batched) ----------------
__global__ __launch_bounds__(256) void av_kernel(
    const float* __restrict__ attn, const float* __restrict__ V,
    float* __restrict__ ctx)
{
    const int z = blockIdx.z;
    const int b = z >> 3, h = z & 7;
    const float* A = attn + (size_t)z * 1024 * 1024;
    const float* B = V + (size_t)b * 1024 * 4096 + (size_t)h * 512;
    float* C = ctx + (size_t)b * 1024 * 4096 + (size_t)h * 512;
    gemm_mma<false, false>(A, 1024, B, 4096, C, 4096, 1024, nullptr);
}

// ---------------------------------------------------------------------------
extern "C" void kernel_launch(void* const* d_in, const int* in_sizes, int n_in,
                              void* d_out, int out_size)
{
    const float* v_ip = (const float*)d_in[0];
    const float* k_ip = (const float*)d_in[1];
    const float* q_ip = (const float*)d_in[2];
    const float* mask = (const float*)d_in[3];
    const float* wq   = (const float*)d_in[4];
    const float* bq   = (const float*)d_in[5];
    const float* wk   = (const float*)d_in[6];
    const float* bk   = (const float*)d_in[7];
    const float* wv   = (const float*)d_in[8];
    const float* bv   = (const float*)d_in[9];
    const float* wo   = (const float*)d_in[10];
    const float* bo   = (const float*)d_in[11];

    float *Q, *K, *V, *CTX, *ATTN_FB;
    cudaGetSymbolAddress((void**)&Q,   g_q);
    cudaGetSymbolAddress((void**)&K,   g_k);
    cudaGetSymbolAddress((void**)&V,   g_v);
    cudaGetSymbolAddress((void**)&CTX, g_ctx);
    cudaGetSymbolAddress((void**)&ATTN_FB, g_attn_fb);

    const size_t OUT_ELEMS  = 8UL * 1024 * 512;
    const size_t ATTN_ELEMS = 64UL * 1024 * 1024;
    float* out = (float*)d_out;
    float* attn = ((size_t)out_size >= OUT_ELEMS + ATTN_ELEMS)
                      ? (out + OUT_ELEMS)
                      : ATTN_FB;

    // 1) projections: (8192x512)@(512x4096)
    {
        dim3 grid(4096 / BN, 8192 / BM);
        proj_kernel<<<grid, 256>>>(q_ip, wq, bq, Q, 512, 4096);
        proj_kernel<<<grid, 256>>>(k_ip, wk, bk, K, 512, 4096);
        proj_kernel<<<grid, 256>>>(v_ip, wv, bv, V, 512, 4096);
    }

    // 2) logits = Q K^T per (b,h)
    {
        dim3 grid(1024 / BN, 1024 / BM, 64);
        qk_kernel<<<grid, 256>>>(Q, K, attn);
    }

    // 3) masked softmax in place
    softmax_kernel<<<64 * 1024, 256>>>(attn, mask);

    // 4) ctx = attn @ V
    {
        dim3 grid(512 / BN, 1024 / BM, 64);
        av_kernel<<<grid, 256>>>(attn, V, CTX);
    }

    // 5) out = ctx @ wo + bo
    {
        dim3 grid(512 / BN, 8192 / BM);
        proj_kernel<<<grid, 256>>>(CTX, wo, bo, out, 4096, 512);
    }
}

// round 7
// speedup vs baseline: 3.4889x; 2.0629x over previous
#include <cuda_runtime.h>
#include <cuda_bf16.h>
#include <math.h>
#include <stdint.h>

using bf16 = __nv_bfloat16;

// ================= device scratch (no allocations allowed) =================
__device__ bf16 g_xh[8192UL * 512],  g_xl[8192UL * 512];
__device__ bf16 g_wth[4096UL * 512], g_wtl[4096UL * 512];   // W^T / Wo^T (reused)
__device__ bf16 g_qh[8192UL * 4096], g_ql[8192UL * 4096];
__device__ bf16 g_kh[8192UL * 4096], g_kl[8192UL * 4096];
__device__ bf16 g_vh[8192UL * 4096], g_vl[8192UL * 4096];
__device__ bf16 g_vth[64UL * 512 * 1024], g_vtl[64UL * 512 * 1024];
__device__ bf16 g_ph[64UL * 1024 * 1024], g_pl[64UL * 1024 * 1024];
__device__ bf16 g_ch[8192UL * 4096], g_cl[8192UL * 4096];
__device__ float g_attn_fb[64UL * 1024 * 1024];

// ================= helpers =================
__device__ __forceinline__ uint32_t smem_u32(const void* p) {
    return (uint32_t)__cvta_generic_to_shared(p);
}
__device__ __forceinline__ void ldsm4(uint32_t* r, uint32_t a) {
    asm volatile("ldmatrix.sync.aligned.m8n8.x4.shared.b16 {%0,%1,%2,%3},[%4];\n"
        : "=r"(r[0]), "=r"(r[1]), "=r"(r[2]), "=r"(r[3]) : "r"(a));
}
__device__ __forceinline__ void mma_bf16(float* d, const uint32_t* a, const uint32_t* b) {
    asm volatile(
        "mma.sync.aligned.m16n8k16.row.col.f32.bf16.bf16.f32 "
        "{%0,%1,%2,%3},{%4,%5,%6,%7},{%8,%9},{%0,%1,%2,%3};\n"
        : "+f"(d[0]), "+f"(d[1]), "+f"(d[2]), "+f"(d[3])
        : "r"(a[0]), "r"(a[1]), "r"(a[2]), "r"(a[3]), "r"(b[0]), "r"(b[1]));
}
__device__ __forceinline__ void cpasync16(uint32_t dst, const void* src) {
    asm volatile("cp.async.cg.shared.global [%0], [%1], 16;" :: "r"(dst), "l"(src));
}
#define CP_COMMIT() asm volatile("cp.async.commit_group;" ::: "memory")
#define CP_WAIT1()  asm volatile("cp.async.wait_group 1;" ::: "memory")

__device__ __forceinline__ void split_bf16(float x, bf16& h, bf16& l) {
    h = __float2bfloat16(x);
    l = __float2bfloat16(x - __bfloat162float(h));
}

// ================= bf16x3 cp.async pipelined GEMM =================
// C[MxN] = A(hi/lo bf16, K-major, lda) * B(hi/lo bf16, [n][k] K-major, ldb)^T
// Block tile 128x128x32, 8 warps (64x32 each), 2-stage cp.async pipeline.
// smem per stage: Ah,Al,Bh,Bl each 128 rows * 80B = 10240B -> 40960B; x2 = 81920B.
#define STAGE_BYTES 40960
#define SMEM_GEMM   81920

__device__ __forceinline__ void load_stage(
    uint32_t sbase, const bf16* __restrict__ Ah, const bf16* __restrict__ Al, int lda,
    const bf16* __restrict__ Bh, const bf16* __restrict__ Bl, int ldb,
    int m0, int n0, int k0)
{
    const int tid = threadIdx.x;
#pragma unroll
    for (int i = 0; i < 2; i++) {
        const int chunk = tid + i * 256;
        const int row = chunk >> 2;
        const int cb  = (chunk & 3) * 16;   // smem byte offset in row
        const int ce  = (chunk & 3) * 8;    // gmem element offset
        const uint32_t so = sbase + row * 80 + cb;
        cpasync16(so,          Ah + (size_t)(m0 + row) * lda + k0 + ce);
        cpasync16(so + 10240,  Al + (size_t)(m0 + row) * lda + k0 + ce);
        cpasync16(so + 20480,  Bh + (size_t)(n0 + row) * ldb + k0 + ce);
        cpasync16(so + 30720,  Bl + (size_t)(n0 + row) * ldb + k0 + ce);
    }
}

template <int OUTMODE /*0=f32, 1=bf16 hi/lo*/, bool BIAS>
__device__ __forceinline__ void gemm_core(
    const bf16* __restrict__ Ah, const bf16* __restrict__ Al, int lda,
    const bf16* __restrict__ Bh, const bf16* __restrict__ Bl, int ldb,
    float* __restrict__ C, bf16* __restrict__ Ch, bf16* __restrict__ Cl, int ldc,
    int K, const float* __restrict__ bias)
{
    extern __shared__ char smem[];
    const uint32_t sb = smem_u32(smem);
    const int tid = threadIdx.x, lane = tid & 31, warp = tid >> 5;
    const int wm = warp >> 2, wn = warp & 3;
    const int m0 = blockIdx.y * 128, n0 = blockIdx.x * 128;

    float acc[4][4][4] = {};

    // preload stage 0 and 1 (K >= 512 -> T >= 16 always)
    load_stage(sb,               Ah, Al, lda, Bh, Bl, ldb, m0, n0, 0);
    CP_COMMIT();
    load_stage(sb + STAGE_BYTES, Ah, Al, lda, Bh, Bl, ldb, m0, n0, 32);
    CP_COMMIT();

    const int T = K >> 5;
    const int offA = (lane & 15) * 80 + (lane >> 4) * 16;
    const int offB = (((lane >> 4) & 1) * 8 + (lane & 7)) * 80 + ((lane >> 3) & 1) * 16;

    for (int t = 0; t < T; t++) {
        CP_WAIT1();
        __syncthreads();
        const uint32_t st = sb + (t & 1) * STAGE_BYTES;
        const uint32_t baseAh = st + wm * 64 * 80 + offA;
        const uint32_t baseAl = baseAh + 10240;
        const uint32_t baseBh = st + 20480 + wn * 32 * 80 + offB;
        const uint32_t baseBl = baseBh + 10240;

#pragma unroll
        for (int ks = 0; ks < 2; ks++) {
            uint32_t bh[2][4], bl[2][4], af[4][4];
            ldsm4(bh[0], baseBh + ks * 32);
            ldsm4(bh[1], baseBh + 16 * 80 + ks * 32);
            ldsm4(bl[0], baseBl + ks * 32);
            ldsm4(bl[1], baseBl + 16 * 80 + ks * 32);
#pragma unroll
            for (int mi = 0; mi < 4; mi++)
                ldsm4(af[mi], baseAh + mi * 16 * 80 + ks * 32);
#pragma unroll
            for (int mi = 0; mi < 4; mi++)
#pragma unroll
                for (int ni = 0; ni < 4; ni++) {
                    mma_bf16(acc[mi][ni], af[mi], &bh[ni >> 1][(ni & 1) * 2]);  // hi*hi
                    mma_bf16(acc[mi][ni], af[mi], &bl[ni >> 1][(ni & 1) * 2]);  // hi*lo
                }
#pragma unroll
            for (int mi = 0; mi < 4; mi++)
                ldsm4(af[mi], baseAl + mi * 16 * 80 + ks * 32);                 // reuse regs
#pragma unroll
            for (int mi = 0; mi < 4; mi++)
#pragma unroll
                for (int ni = 0; ni < 4; ni++)
                    mma_bf16(acc[mi][ni], af[mi], &bh[ni >> 1][(ni & 1) * 2]);  // lo*hi
        }
        __syncthreads();
        if (t + 2 < T)
            load_stage(sb + (t & 1) * STAGE_BYTES, Ah, Al, lda, Bh, Bl, ldb,
                       m0, n0, (t + 2) * 32);
        CP_COMMIT();   // commit every iter (possibly empty) to keep group accounting uniform
    }

    // ---- epilogue ----
    const int mw = m0 + wm * 64, nw = n0 + wn * 32;
#pragma unroll
    for (int mi = 0; mi < 4; mi++) {
        const int r0 = mw + mi * 16 + (lane >> 2);
#pragma unroll
        for (int ni = 0; ni < 4; ni++) {
            const int c = nw + ni * 8 + (lane & 3) * 2;
            float v0 = acc[mi][ni][0], v1 = acc[mi][ni][1];
            float v2 = acc[mi][ni][2], v3 = acc[mi][ni][3];
            if (BIAS) {
                float2 bb = *reinterpret_cast<const float2*>(&bias[c]);
                v0 += bb.x; v1 += bb.y; v2 += bb.x; v3 += bb.y;
            }
            if (OUTMODE == 0) {
                float2 o0; o0.x = v0; o0.y = v1;
                float2 o1; o1.x = v2; o1.y = v3;
                *reinterpret_cast<float2*>(&C[(size_t)r0 * ldc + c]) = o0;
                *reinterpret_cast<float2*>(&C[(size_t)(r0 + 8) * ldc + c]) = o1;
            } else {
                bf16 h, l;
                __nv_bfloat162 hh, ll;
                split_bf16(v0, h, l); hh.x = h; ll.x = l;
                split_bf16(v1, h, l); hh.y = h; ll.y = l;
                *reinterpret_cast<__nv_bfloat162*>(&Ch[(size_t)r0 * ldc + c]) = hh;
                *reinterpret_cast<__nv_bfloat162*>(&Cl[(size_t)r0 * ldc + c]) = ll;
                split_bf16(v2, h, l); hh.x = h; ll.x = l;
                split_bf16(v3, h, l); hh.y = h; ll.y = l;
                *reinterpret_cast<__nv_bfloat162*>(&Ch[(size_t)(r0 + 8) * ldc + c]) = hh;
                *reinterpret_cast<__nv_bfloat162*>(&Cl[(size_t)(r0 + 8) * ldc + c]) = ll;
            }
        }
    }
}

// ---------------- GEMM wrappers ----------------
__global__ __launch_bounds__(256, 2) void gemm_proj_kernel(
    const bf16* Xh, const bf16* Xl, const bf16* Wth, const bf16* Wtl,
    bf16* Ch, bf16* Cl, const float* bias)
{
    gemm_core<1, true>(Xh, Xl, 512, Wth, Wtl, 512, nullptr, Ch, Cl, 4096, 512, bias);
}

__global__ __launch_bounds__(256, 2) void gemm_qk_kernel(
    const bf16* Qh, const bf16* Ql, const bf16* Kh, const bf16* Kl, float* logits)
{
    const int z = blockIdx.z, b = z >> 3, h = z & 7;
    const size_t ao = (size_t)b * 1024 * 4096 + (size_t)h * 512;
    gemm_core<0, false>(Qh + ao, Ql + ao, 4096, Kh + ao, Kl + ao, 4096,
                        logits + ((size_t)z << 20), nullptr, nullptr, 1024, 512, nullptr);
}

__global__ __launch_bounds__(256, 2) void gemm_av_kernel(
    const bf16* Ph, const bf16* Pl, const bf16* VTh, const bf16* VTl,
    bf16* Ch, bf16* Cl)
{
    const int z = blockIdx.z, b = z >> 3, h = z & 7;
    const size_t po = (size_t)z << 20;
    const size_t vo = (size_t)z * 512 * 1024;
    const size_t co = (size_t)b * 1024 * 4096 + (size_t)h * 512;
    gemm_core<1, false>(Ph + po, Pl + po, 1024, VTh + vo, VTl + vo, 1024,
                        nullptr, Ch + co, Cl + co, 4096, 1024, nullptr);
}

__global__ __launch_bounds__(256, 2) void gemm_wo_kernel(
    const bf16* Ah, const bf16* Al, const bf16* Wth, const bf16* Wtl,
    float* out, const float* bo)
{
    gemm_core<0, true>(Ah, Al, 4096, Wth, Wtl, 4096, out, nullptr, nullptr, 512, 4096, bo);
}

// ---------------- prep kernels ----------------
__global__ __launch_bounds__(256) void split_kernel(
    const float* __restrict__ in, bf16* __restrict__ h, bf16* __restrict__ l, int n4)
{
    const int i = blockIdx.x * 256 + threadIdx.x;
    if (i >= n4) return;
    float4 v = reinterpret_cast<const float4*>(in)[i];
    bf16 h0, l0, h1, l1, h2, l2, h3, l3;
    split_bf16(v.x, h0, l0); split_bf16(v.y, h1, l1);
    split_bf16(v.z, h2, l2); split_bf16(v.w, h3, l3);
    __nv_bfloat162 a, b2;
    a.x = h0; a.y = h1; b2.x = h2; b2.y = h3;
    reinterpret_cast<__nv_bfloat162*>(h)[2 * i] = a;
    reinterpret_cast<__nv_bfloat162*>(h)[2 * i + 1] = b2;
    a.x = l0; a.y = l1; b2.x = l2; b2.y = l3;
    reinterpret_cast<__nv_bfloat162*>(l)[2 * i] = a;
    reinterpret_cast<__nv_bfloat162*>(l)[2 * i + 1] = b2;
}

// transpose + split: src fp32 [R0][C0] -> dst bf16 [C0][R0] (hi/lo)
__global__ __launch_bounds__(256) void tsplit_kernel(
    const float* __restrict__ src, bf16* __restrict__ th, bf16* __restrict__ tl,
    int R0, int C0)
{
    __shared__ float tile[32][33];
    const int c0 = blockIdx.x * 32, r0 = blockIdx.y * 32;
    const int tx = threadIdx.x & 31, ty0 = threadIdx.x >> 5;
#pragma unroll
    for (int j = 0; j < 4; j++) {
        const int ty = ty0 * 4 + j;
        tile[ty][tx] = src[(size_t)(r0 + ty) * C0 + c0 + tx];
    }
    __syncthreads();
#pragma unroll
    for (int j = 0; j < 4; j++) {
        const int ty = ty0 * 4 + j;
        float v = tile[tx][ty];
        bf16 h, l; split_bf16(v, h, l);
        th[(size_t)(c0 + ty) * R0 + r0 + tx] = h;
        tl[(size_t)(c0 + ty) * R0 + r0 + tx] = l;
    }
}

// per-(b,h) transpose of V (bf16 hi/lo): [s][d] -> VT[z][d][s]
__global__ __launch_bounds__(256) void vtrans_kernel(
    const bf16* __restrict__ Vh, const bf16* __restrict__ Vl,
    bf16* __restrict__ VTh, bf16* __restrict__ VTl)
{
    const int z = blockIdx.z, b = z >> 3, h = z & 7;
    const int s0 = blockIdx.x * 32, d0 = blockIdx.y * 32;
    __shared__ bf16 th[32][33], tl2[32][33];
    const int tx = threadIdx.x & 31, ty0 = threadIdx.x >> 5;
    const size_t srcb = (size_t)(b * 1024) * 4096 + (size_t)h * 512;
#pragma unroll
    for (int j = 0; j < 4; j++) {
        const int ty = ty0 * 4 + j;
        th[ty][tx]  = Vh[srcb + (size_t)(s0 + ty) * 4096 + d0 + tx];
        tl2[ty][tx] = Vl[srcb + (size_t)(s0 + ty) * 4096 + d0 + tx];
    }
    __syncthreads();
    const size_t dstb = (size_t)z * 512 * 1024;
#pragma unroll
    for (int j = 0; j < 4; j++) {
        const int ty = ty0 * 4 + j;
        VTh[dstb + (size_t)(d0 + ty) * 1024 + s0 + tx] = th[tx][ty];
        VTl[dstb + (size_t)(d0 + ty) * 1024 + s0 + tx] = tl2[tx][ty];
    }
}

// ---------------- masked softmax: fp32 attn + bf16 hi/lo P ----------------
__global__ __launch_bounds__(256) void softmax_kernel(
    float* __restrict__ attn, const float* __restrict__ mask,
    bf16* __restrict__ Ph, bf16* __restrict__ Pl)
{
    const int r = blockIdx.x;           // ((b*8+h)*1024)+q
    const int q = r & 1023;
    const int b = r >> 13;
    const int tid = threadIdx.x;
    float* row = attn + (size_t)r * 1024;
    const float* mrow = mask + ((size_t)b * 1024 + q) * 1024;
    const float scale = 0.044194173824159216f;  // 1/sqrt(512)

    float4 lg = *reinterpret_cast<const float4*>(&row[tid * 4]);
    float4 mk = *reinterpret_cast<const float4*>(&mrow[tid * 4]);
    float vals[4] = {
        lg.x * scale + mk.x * (-1e9f), lg.y * scale + mk.y * (-1e9f),
        lg.z * scale + mk.z * (-1e9f), lg.w * scale + mk.w * (-1e9f)};

    float mx = fmaxf(fmaxf(vals[0], vals[1]), fmaxf(vals[2], vals[3]));
    __shared__ float sred[8];
#pragma unroll
    for (int o = 16; o > 0; o >>= 1)
        mx = fmaxf(mx, __shfl_xor_sync(0xffffffffu, mx, o));
    if ((tid & 31) == 0) sred[tid >> 5] = mx;
    __syncthreads();
    if (tid < 32) {
        float v = (tid < 8) ? sred[tid] : -INFINITY;
#pragma unroll
        for (int o = 4; o > 0; o >>= 1)
            v = fmaxf(v, __shfl_xor_sync(0xffffffffu, v, o));
        if (tid == 0) sred[0] = v;
    }
    __syncthreads();
    mx = sred[0];

    float s = 0.f;
#pragma unroll
    for (int j = 0; j < 4; j++) { vals[j] = __expf(vals[j] - mx); s += vals[j]; }
#pragma unroll
    for (int o = 16; o > 0; o >>= 1)
        s += __shfl_xor_sync(0xffffffffu, s, o);
    __syncthreads();
    if ((tid & 31) == 0) sred[tid >> 5] = s;
    __syncthreads();
    if (tid < 32) {
        float v = (tid < 8) ? sred[tid] : 0.f;
#pragma unroll
        for (int o = 4; o > 0; o >>= 1)
            v += __shfl_xor_sync(0xffffffffu, v, o);
        if (tid == 0) sred[0] = v;
    }
    __syncthreads();
    const float inv = 1.0f / sred[0];

    float4 o4;
    o4.x = vals[0] * inv; o4.y = vals[1] * inv;
    o4.z = vals[2] * inv; o4.w = vals[3] * inv;
    *reinterpret_cast<float4*>(&row[tid * 4]) = o4;

    bf16 h0, l0, h1, l1, h2, l2, h3, l3;
    split_bf16(o4.x, h0, l0); split_bf16(o4.y, h1, l1);
    split_bf16(o4.z, h2, l2); split_bf16(o4.w, h3, l3);
    const size_t base = (size_t)r * 1024 + tid * 4;
    __nv_bfloat162 a, b2;
    a.x = h0; a.y = h1; b2.x = h2; b2.y = h3;
    *reinterpret_cast<__nv_bfloat162*>(&Ph[base]) = a;
    *reinterpret_cast<__nv_bfloat162*>(&Ph[base + 2]) = b2;
    a.x = l0; a.y = l1; b2.x = l2; b2.y = l3;
    *reinterpret_cast<__nv_bfloat162*>(&Pl[base]) = a;
    *reinterpret_cast<__nv_bfloat162*>(&Pl[base + 2]) = b2;
}

// ===========================================================================
extern "C" void kernel_launch(void* const* d_in, const int* in_sizes, int n_in,
                              void* d_out, int out_size)
{
    const float* v_ip = (const float*)d_in[0];
    const float* k_ip = (const float*)d_in[1];
    const float* q_ip = (const float*)d_in[2];
    const float* mask = (const float*)d_in[3];
    const float* wq   = (const float*)d_in[4];
    const float* bq   = (const float*)d_in[5];
    const float* wk   = (const float*)d_in[6];
    const float* bk   = (const float*)d_in[7];
    const float* wv   = (const float*)d_in[8];
    const float* bv   = (const float*)d_in[9];
    const float* wo   = (const float*)d_in[10];
    const float* bo   = (const float*)d_in[11];

    bf16 *xh, *xl, *wth, *wtl, *qh, *ql, *kh, *kl, *vh, *vl, *vth, *vtl, *ph, *pl, *ch, *cl;
    float* fb;
    cudaGetSymbolAddress((void**)&xh, g_xh);   cudaGetSymbolAddress((void**)&xl, g_xl);
    cudaGetSymbolAddress((void**)&wth, g_wth); cudaGetSymbolAddress((void**)&wtl, g_wtl);
    cudaGetSymbolAddress((void**)&qh, g_qh);   cudaGetSymbolAddress((void**)&ql, g_ql);
    cudaGetSymbolAddress((void**)&kh, g_kh);   cudaGetSymbolAddress((void**)&kl, g_kl);
    cudaGetSymbolAddress((void**)&vh, g_vh);   cudaGetSymbolAddress((void**)&vl, g_vl);
    cudaGetSymbolAddress((void**)&vth, g_vth); cudaGetSymbolAddress((void**)&vtl, g_vtl);
    cudaGetSymbolAddress((void**)&ph, g_ph);   cudaGetSymbolAddress((void**)&pl, g_pl);
    cudaGetSymbolAddress((void**)&ch, g_ch);   cudaGetSymbolAddress((void**)&cl, g_cl);
    cudaGetSymbolAddress((void**)&fb, g_attn_fb);

    cudaFuncSetAttribute(gemm_proj_kernel, cudaFuncAttributeMaxDynamicSharedMemorySize, SMEM_GEMM);
    cudaFuncSetAttribute(gemm_qk_kernel,   cudaFuncAttributeMaxDynamicSharedMemorySize, SMEM_GEMM);
    cudaFuncSetAttribute(gemm_av_kernel,   cudaFuncAttributeMaxDynamicSharedMemorySize, SMEM_GEMM);
    cudaFuncSetAttribute(gemm_wo_kernel,   cudaFuncAttributeMaxDynamicSharedMemorySize, SMEM_GEMM);

    const size_t OUT_ELEMS  = 8UL * 1024 * 512;
    const size_t ATTN_ELEMS = 64UL * 1024 * 1024;
    float* out  = (float*)d_out;
    float* attn = ((size_t)out_size >= OUT_ELEMS + ATTN_ELEMS) ? (out + OUT_ELEMS) : fb;

    const int n4x = (8192 * 512) / 4;
    const dim3 pgrid(32, 64);            // proj: N=4096/128, M=8192/128
    const dim3 wgrid(128, 16);           // W^T:  C0=4096/32, R0=512/32

    // Q projection
    split_kernel<<<(n4x + 255) / 256, 256>>>(q_ip, xh, xl, n4x);
    tsplit_kernel<<<wgrid, 256>>>(wq, wth, wtl, 512, 4096);
    gemm_proj_kernel<<<pgrid, 256, SMEM_GEMM>>>(xh, xl, wth, wtl, qh, ql, bq);
    // K projection
    split_kernel<<<(n4x + 255) / 256, 256>>>(k_ip, xh, xl, n4x);
    tsplit_kernel<<<wgrid, 256>>>(wk, wth, wtl, 512, 4096);
    gemm_proj_kernel<<<pgrid, 256, SMEM_GEMM>>>(xh, xl, wth, wtl, kh, kl, bk);
    // V projection
    split_kernel<<<(n4x + 255) / 256, 256>>>(v_ip, xh, xl, n4x);
    tsplit_kernel<<<wgrid, 256>>>(wv, wth, wtl, 512, 4096);
    gemm_proj_kernel<<<pgrid, 256, SMEM_GEMM>>>(xh, xl, wth, wtl, vh, vl, bv);

    // V^T per (b,h)
    vtrans_kernel<<<dim3(32, 16, 64), 256>>>(vh, vl, vth, vtl);

    // logits = Q K^T
    gemm_qk_kernel<<<dim3(8, 8, 64), 256, SMEM_GEMM>>>(qh, ql, kh, kl, attn);

    // masked softmax -> attn fp32 + P bf16 hi/lo
    softmax_kernel<<<64 * 1024, 256>>>(attn, mask, ph, pl);

    // ctx = P @ V
    gemm_av_kernel<<<dim3(4, 8, 64), 256, SMEM_GEMM>>>(ph, pl, vth, vtl, ch, cl);

    // out = ctx @ wo + bo
    tsplit_kernel<<<dim3(16, 128), 256>>>(wo, wth, wtl, 4096, 512);
    gemm_wo_kernel<<<dim3(4, 64), 256, SMEM_GEMM>>>(ch, cl, wth, wtl, out, bo);
}